// round 5
// baseline (speedup 1.0000x reference)
#include <cuda_runtime.h>
#include <cuda_bf16.h>
#include <cstdint>

// ---------------------------------------------------------------------------
// FeaturePropagation (PointNet++ FP layer), fp32 baseline
//   B=16, N1=4096, N2=1024, C1=128, C2=256, mlp=[256,256]
// Pipeline:
//   1) interp_kernel: 3-NN inverse-distance interpolation of feat2 onto xyz1,
//      concat with feat1 -> x0 (M=65536, K0=384)
//   2) gemm_fused:    x0 @ W0 + b0 -> relu -> BN  -> x1 (M x 256)
//   3) gemm_fused:    x1 @ W1 + b1 -> relu -> BN  -> out (M x 256)
// ---------------------------------------------------------------------------

#define B_   16
#define N1_  4096
#define N2_  1024
#define C1_  128
#define C2_  256
#define CIN_ 384      // C2 + C1
#define CH_  256      // mlp widths
#define M_   (B_ * N1_)
#define BN_EPS 1e-3f

// scratch (allocation-free rule: device globals)
__device__ float g_x0[(size_t)M_ * CIN_];   // ~100.7 MB
__device__ float g_x1[(size_t)M_ * CH_];    // ~67 MB

// ---------------------------------------------------------------------------
// Kernel 1: 3-NN interpolate + concat
// grid: (N1/PPB, B), block: PPB threads (PPB = 128)
// ---------------------------------------------------------------------------
#define PPB 128

__global__ __launch_bounds__(PPB) void interp_kernel(
    const float* __restrict__ xyz1,   // (B, N1, 3)
    const float* __restrict__ xyz2,   // (B, N2, 3)
    const float* __restrict__ feat1,  // (B, N1, C1)
    const float* __restrict__ feat2,  // (B, N2, C2)
    float* __restrict__ x0)           // (B*N1, CIN)
{
    __shared__ float sx[N2_];
    __shared__ float sy[N2_];
    __shared__ float sz[N2_];
    __shared__ float sb2[N2_];
    __shared__ int   s_idx[PPB][3];
    __shared__ float s_w[PPB][3];

    const int tid = threadIdx.x;
    const int b   = blockIdx.y;
    const int n0  = blockIdx.x * PPB;

    // stage xyz2[b] + its squared norms
    for (int j = tid; j < N2_; j += PPB) {
        float x = xyz2[((size_t)b * N2_ + j) * 3 + 0];
        float y = xyz2[((size_t)b * N2_ + j) * 3 + 1];
        float z = xyz2[((size_t)b * N2_ + j) * 3 + 2];
        sx[j] = x; sy[j] = y; sz[j] = z;
        sb2[j] = x * x + y * y + z * z;
    }
    __syncthreads();

    // phase 1: each thread finds top-3 nearest for one query point
    {
        const int n = n0 + tid;
        const float qx = xyz1[((size_t)b * N1_ + n) * 3 + 0];
        const float qy = xyz1[((size_t)b * N1_ + n) * 3 + 1];
        const float qz = xyz1[((size_t)b * N1_ + n) * 3 + 2];
        const float a2 = qx * qx + qy * qy + qz * qz;

        float d0 = 1e30f, d1 = 1e30f, d2v = 1e30f;
        int   i0 = 0, i1 = 0, i2 = 0;

        #pragma unroll 4
        for (int j = 0; j < N2_; j++) {
            float ab = qx * sx[j] + qy * sy[j] + qz * sz[j];
            float d  = fmaxf(a2 - 2.0f * ab + sb2[j], 0.0f);
            if (d < d0) {
                d2v = d1; i2 = i1;
                d1 = d0;  i1 = i0;
                d0 = d;   i0 = j;
            } else if (d < d1) {
                d2v = d1; i2 = i1;
                d1 = d;   i1 = j;
            } else if (d < d2v) {
                d2v = d;  i2 = j;
            }
        }
        float w0 = 1.0f / (d0  + 1e-10f);
        float w1 = 1.0f / (d1  + 1e-10f);
        float w2 = 1.0f / (d2v + 1e-10f);
        float inv = 1.0f / (w0 + w1 + w2);
        s_idx[tid][0] = i0; s_idx[tid][1] = i1; s_idx[tid][2] = i2;
        s_w[tid][0] = w0 * inv; s_w[tid][1] = w1 * inv; s_w[tid][2] = w2 * inv;
    }
    __syncthreads();

    // phase 2: cooperative gather + concat, coalesced along channels
    const float* f2b = feat2 + (size_t)b * N2_ * C2_;
    const float* f1b = feat1 + (size_t)b * N1_ * C1_;
    for (int p = 0; p < PPB; p++) {
        const int n = n0 + p;
        const int i0 = s_idx[p][0], i1 = s_idx[p][1], i2 = s_idx[p][2];
        const float w0 = s_w[p][0], w1 = s_w[p][1], w2 = s_w[p][2];
        float* dst = x0 + ((size_t)b * N1_ + n) * CIN_;
        const float* r0 = f2b + (size_t)i0 * C2_;
        const float* r1 = f2b + (size_t)i1 * C2_;
        const float* r2 = f2b + (size_t)i2 * C2_;
        #pragma unroll
        for (int c = tid; c < C2_; c += PPB) {
            dst[c] = w0 * r0[c] + w1 * r1[c] + w2 * r2[c];
        }
        // feat1 concat (C1 = PPB = 128 -> one iteration)
        dst[C2_ + tid] = f1b[(size_t)n * C1_ + tid];
    }
}

// ---------------------------------------------------------------------------
// Kernel 2/3: SGEMM  C = fused_bn_relu(A @ W + bias)
//   A: (M, K) row-major, W: (K, N) row-major, C: (M, N)
//   BM=128, BN=128, BK=16, 256 threads, 8x8 per thread
// ---------------------------------------------------------------------------
#define GBM 128
#define GBN 128
#define GBK 16
#define GTM 8
#define GTN 8

__global__ __launch_bounds__(256) void gemm_fused(
    const float* __restrict__ A, const float* __restrict__ W,
    const float* __restrict__ bias, const float* __restrict__ gamma,
    const float* __restrict__ beta, const float* __restrict__ mean,
    const float* __restrict__ var,
    float* __restrict__ C, int M, int N, int K)
{
    __shared__ float As[GBK][GBM];
    __shared__ float Bs[GBK][GBN];

    const int tid = threadIdx.x;
    const int tx = tid & 15;       // n-dir (16)
    const int ty = tid >> 4;       // m-dir (16)
    const int row0 = blockIdx.x * GBM;
    const int col0 = blockIdx.y * GBN;

    // A-tile load map: 128 rows x 16 cols, float4 along K
    const int aRow = tid >> 2;            // 0..63
    const int aCol = (tid & 3) << 2;      // 0,4,8,12
    // B-tile load map: 16 rows x 128 cols, float4 along N
    const int bRow = tid >> 5;            // 0..7
    const int bCol = (tid & 31) << 2;     // 0..124

    float acc[GTM][GTN];
    #pragma unroll
    for (int i = 0; i < GTM; i++)
        #pragma unroll
        for (int j = 0; j < GTN; j++) acc[i][j] = 0.0f;

    for (int k0 = 0; k0 < K; k0 += GBK) {
        #pragma unroll
        for (int r = 0; r < 2; r++) {
            int m = aRow + r * 64;
            float4 v = *(const float4*)(A + (size_t)(row0 + m) * K + k0 + aCol);
            As[aCol + 0][m] = v.x;
            As[aCol + 1][m] = v.y;
            As[aCol + 2][m] = v.z;
            As[aCol + 3][m] = v.w;
        }
        #pragma unroll
        for (int r = 0; r < 2; r++) {
            int kk = bRow + r * 8;
            float4 v = *(const float4*)(W + (size_t)(k0 + kk) * N + col0 + bCol);
            *(float4*)(&Bs[kk][bCol]) = v;
        }
        __syncthreads();

        #pragma unroll
        for (int kk = 0; kk < GBK; kk++) {
            float af[GTM], bf[GTN];
            #pragma unroll
            for (int i = 0; i < GTM; i++) af[i] = As[kk][ty * GTM + i];
            #pragma unroll
            for (int j = 0; j < GTN; j++) bf[j] = Bs[kk][tx * GTN + j];
            #pragma unroll
            for (int i = 0; i < GTM; i++)
                #pragma unroll
                for (int j = 0; j < GTN; j++)
                    acc[i][j] = fmaf(af[i], bf[j], acc[i][j]);
        }
        __syncthreads();
    }

    // epilogue: z = relu(acc + bias); out = scale*z + shift
    float sc[GTN], sh[GTN], bb[GTN];
    #pragma unroll
    for (int j = 0; j < GTN; j++) {
        int n = col0 + tx * GTN + j;
        float s = gamma[n] * rsqrtf(var[n] + BN_EPS);
        sc[j] = s;
        sh[j] = beta[n] - mean[n] * s;
        bb[j] = bias[n];
    }
    #pragma unroll
    for (int i = 0; i < GTM; i++) {
        int m = row0 + ty * GTM + i;
        float* crow = C + (size_t)m * N + col0 + tx * GTN;
        #pragma unroll
        for (int jv = 0; jv < GTN; jv += 4) {
            float4 o;
            float z;
            z = fmaxf(acc[i][jv + 0] + bb[jv + 0], 0.0f); o.x = sc[jv + 0] * z + sh[jv + 0];
            z = fmaxf(acc[i][jv + 1] + bb[jv + 1], 0.0f); o.y = sc[jv + 1] * z + sh[jv + 1];
            z = fmaxf(acc[i][jv + 2] + bb[jv + 2], 0.0f); o.z = sc[jv + 2] * z + sh[jv + 2];
            z = fmaxf(acc[i][jv + 3] + bb[jv + 3], 0.0f); o.w = sc[jv + 3] * z + sh[jv + 3];
            *(float4*)(crow + jv) = o;
        }
    }
}

// ---------------------------------------------------------------------------
// launch
// ---------------------------------------------------------------------------
extern "C" void kernel_launch(void* const* d_in, const int* in_sizes, int n_in,
                              void* d_out, int out_size)
{
    const float* xyz1   = (const float*)d_in[0];
    const float* xyz2   = (const float*)d_in[1];
    const float* feat1  = (const float*)d_in[2];
    const float* feat2  = (const float*)d_in[3];
    const float* W0     = (const float*)d_in[4];
    const float* b0     = (const float*)d_in[5];
    const float* gamma0 = (const float*)d_in[6];
    const float* beta0  = (const float*)d_in[7];
    const float* mean0  = (const float*)d_in[8];
    const float* var0   = (const float*)d_in[9];
    const float* W1     = (const float*)d_in[10];
    const float* b1     = (const float*)d_in[11];
    const float* gamma1 = (const float*)d_in[12];
    const float* beta1  = (const float*)d_in[13];
    const float* mean1  = (const float*)d_in[14];
    const float* var1   = (const float*)d_in[15];
    float* out = (float*)d_out;

    float* x0 = nullptr;
    float* x1 = nullptr;
    cudaGetSymbolAddress((void**)&x0, g_x0);
    cudaGetSymbolAddress((void**)&x1, g_x1);

    // 1) interpolate + concat
    {
        dim3 grid(N1_ / PPB, B_);
        interp_kernel<<<grid, PPB>>>(xyz1, xyz2, feat1, feat2, x0);
    }
    // 2) layer 0: (M,384) @ (384,256)
    {
        dim3 grid(M_ / GBM, CH_ / GBN);
        gemm_fused<<<grid, 256>>>(x0, W0, b0, gamma0, beta0, mean0, var0,
                                  x1, M_, CH_, CIN_);
    }
    // 3) layer 1: (M,256) @ (256,256) -> out
    {
        dim3 grid(M_ / GBM, CH_ / GBN);
        gemm_fused<<<grid, 256>>>(x1, W1, b1, gamma1, beta1, mean1, var1,
                                  out, M_, CH_, CH_);
    }
}

// round 6
// speedup vs baseline: 1.0025x; 1.0025x over previous
#include <cuda_runtime.h>
#include <cuda_bf16.h>
#include <cstdint>

// ---------------------------------------------------------------------------
// FeaturePropagation (PointNet++ FP layer), fp32 baseline
//   B=16, N1=4096, N2=1024, C1=128, C2=256, mlp=[256,256]
// Pipeline:
//   1) interp_kernel: 3-NN inverse-distance interpolation of feat2 onto xyz1,
//      concat with feat1 -> x0 (M=65536, K0=384)
//   2) gemm_fused:    x0 @ W0 + b0 -> relu -> BN  -> x1 (M x 256)
//   3) gemm_fused:    x1 @ W1 + b1 -> relu -> BN  -> out (M x 256)
// ---------------------------------------------------------------------------

#define B_   16
#define N1_  4096
#define N2_  1024
#define C1_  128
#define C2_  256
#define CIN_ 384      // C2 + C1
#define CH_  256      // mlp widths
#define M_   (B_ * N1_)
#define BN_EPS 1e-3f

// scratch (allocation-free rule: device globals)
__device__ float g_x0[(size_t)M_ * CIN_];   // ~100.7 MB
__device__ float g_x1[(size_t)M_ * CH_];    // ~67 MB

// ---------------------------------------------------------------------------
// Kernel 1: 3-NN interpolate + concat
// grid: (N1/PPB, B), block: PPB threads (PPB = 128)
// ---------------------------------------------------------------------------
#define PPB 128

__global__ __launch_bounds__(PPB) void interp_kernel(
    const float* __restrict__ xyz1,   // (B, N1, 3)
    const float* __restrict__ xyz2,   // (B, N2, 3)
    const float* __restrict__ feat1,  // (B, N1, C1)
    const float* __restrict__ feat2,  // (B, N2, C2)
    float* __restrict__ x0)           // (B*N1, CIN)
{
    __shared__ float sx[N2_];
    __shared__ float sy[N2_];
    __shared__ float sz[N2_];
    __shared__ float sb2[N2_];
    __shared__ int   s_idx[PPB][3];
    __shared__ float s_w[PPB][3];

    const int tid = threadIdx.x;
    const int b   = blockIdx.y;
    const int n0  = blockIdx.x * PPB;

    // stage xyz2[b] + its squared norms
    for (int j = tid; j < N2_; j += PPB) {
        float x = xyz2[((size_t)b * N2_ + j) * 3 + 0];
        float y = xyz2[((size_t)b * N2_ + j) * 3 + 1];
        float z = xyz2[((size_t)b * N2_ + j) * 3 + 2];
        sx[j] = x; sy[j] = y; sz[j] = z;
        sb2[j] = x * x + y * y + z * z;
    }
    __syncthreads();

    // phase 1: each thread finds top-3 nearest for one query point
    {
        const int n = n0 + tid;
        const float qx = xyz1[((size_t)b * N1_ + n) * 3 + 0];
        const float qy = xyz1[((size_t)b * N1_ + n) * 3 + 1];
        const float qz = xyz1[((size_t)b * N1_ + n) * 3 + 2];
        const float a2 = qx * qx + qy * qy + qz * qz;

        float d0 = 1e30f, d1 = 1e30f, d2v = 1e30f;
        int   i0 = 0, i1 = 0, i2 = 0;

        #pragma unroll 4
        for (int j = 0; j < N2_; j++) {
            float ab = qx * sx[j] + qy * sy[j] + qz * sz[j];
            float d  = fmaxf(a2 - 2.0f * ab + sb2[j], 0.0f);
            if (d < d0) {
                d2v = d1; i2 = i1;
                d1 = d0;  i1 = i0;
                d0 = d;   i0 = j;
            } else if (d < d1) {
                d2v = d1; i2 = i1;
                d1 = d;   i1 = j;
            } else if (d < d2v) {
                d2v = d;  i2 = j;
            }
        }
        float w0 = 1.0f / (d0  + 1e-10f);
        float w1 = 1.0f / (d1  + 1e-10f);
        float w2 = 1.0f / (d2v + 1e-10f);
        float inv = 1.0f / (w0 + w1 + w2);
        s_idx[tid][0] = i0; s_idx[tid][1] = i1; s_idx[tid][2] = i2;
        s_w[tid][0] = w0 * inv; s_w[tid][1] = w1 * inv; s_w[tid][2] = w2 * inv;
    }
    __syncthreads();

    // phase 2: cooperative gather + concat, coalesced along channels
    const float* f2b = feat2 + (size_t)b * N2_ * C2_;
    const float* f1b = feat1 + (size_t)b * N1_ * C1_;
    for (int p = 0; p < PPB; p++) {
        const int n = n0 + p;
        const int i0 = s_idx[p][0], i1 = s_idx[p][1], i2 = s_idx[p][2];
        const float w0 = s_w[p][0], w1 = s_w[p][1], w2 = s_w[p][2];
        float* dst = x0 + ((size_t)b * N1_ + n) * CIN_;
        const float* r0 = f2b + (size_t)i0 * C2_;
        const float* r1 = f2b + (size_t)i1 * C2_;
        const float* r2 = f2b + (size_t)i2 * C2_;
        #pragma unroll
        for (int c = tid; c < C2_; c += PPB) {
            dst[c] = w0 * r0[c] + w1 * r1[c] + w2 * r2[c];
        }
        // feat1 concat (C1 = PPB = 128 -> one iteration)
        dst[C2_ + tid] = f1b[(size_t)n * C1_ + tid];
    }
}

// ---------------------------------------------------------------------------
// Kernel 2/3: SGEMM  C = fused_bn_relu(A @ W + bias)
//   A: (M, K) row-major, W: (K, N) row-major, C: (M, N)
//   BM=128, BN=128, BK=16, 256 threads, 8x8 per thread
// ---------------------------------------------------------------------------
#define GBM 128
#define GBN 128
#define GBK 16
#define GTM 8
#define GTN 8

__global__ __launch_bounds__(256) void gemm_fused(
    const float* __restrict__ A, const float* __restrict__ W,
    const float* __restrict__ bias, const float* __restrict__ gamma,
    const float* __restrict__ beta, const float* __restrict__ mean,
    const float* __restrict__ var,
    float* __restrict__ C, int M, int N, int K)
{
    __shared__ float As[GBK][GBM];
    __shared__ float Bs[GBK][GBN];

    const int tid = threadIdx.x;
    const int tx = tid & 15;       // n-dir (16)
    const int ty = tid >> 4;       // m-dir (16)
    const int row0 = blockIdx.x * GBM;
    const int col0 = blockIdx.y * GBN;

    // A-tile load map: 128 rows x 16 cols, float4 along K
    const int aRow = tid >> 2;            // 0..63
    const int aCol = (tid & 3) << 2;      // 0,4,8,12
    // B-tile load map: 16 rows x 128 cols, float4 along N
    const int bRow = tid >> 5;            // 0..7
    const int bCol = (tid & 31) << 2;     // 0..124

    float acc[GTM][GTN];
    #pragma unroll
    for (int i = 0; i < GTM; i++)
        #pragma unroll
        for (int j = 0; j < GTN; j++) acc[i][j] = 0.0f;

    for (int k0 = 0; k0 < K; k0 += GBK) {
        #pragma unroll
        for (int r = 0; r < 2; r++) {
            int m = aRow + r * 64;
            float4 v = *(const float4*)(A + (size_t)(row0 + m) * K + k0 + aCol);
            As[aCol + 0][m] = v.x;
            As[aCol + 1][m] = v.y;
            As[aCol + 2][m] = v.z;
            As[aCol + 3][m] = v.w;
        }
        #pragma unroll
        for (int r = 0; r < 2; r++) {
            int kk = bRow + r * 8;
            float4 v = *(const float4*)(W + (size_t)(k0 + kk) * N + col0 + bCol);
            *(float4*)(&Bs[kk][bCol]) = v;
        }
        __syncthreads();

        #pragma unroll
        for (int kk = 0; kk < GBK; kk++) {
            float af[GTM], bf[GTN];
            #pragma unroll
            for (int i = 0; i < GTM; i++) af[i] = As[kk][ty * GTM + i];
            #pragma unroll
            for (int j = 0; j < GTN; j++) bf[j] = Bs[kk][tx * GTN + j];
            #pragma unroll
            for (int i = 0; i < GTM; i++)
                #pragma unroll
                for (int j = 0; j < GTN; j++)
                    acc[i][j] = fmaf(af[i], bf[j], acc[i][j]);
        }
        __syncthreads();
    }

    // epilogue: z = relu(acc + bias); out = scale*z + shift
    float sc[GTN], sh[GTN], bb[GTN];
    #pragma unroll
    for (int j = 0; j < GTN; j++) {
        int n = col0 + tx * GTN + j;
        float s = gamma[n] * rsqrtf(var[n] + BN_EPS);
        sc[j] = s;
        sh[j] = beta[n] - mean[n] * s;
        bb[j] = bias[n];
    }
    #pragma unroll
    for (int i = 0; i < GTM; i++) {
        int m = row0 + ty * GTM + i;
        float* crow = C + (size_t)m * N + col0 + tx * GTN;
        #pragma unroll
        for (int jv = 0; jv < GTN; jv += 4) {
            float4 o;
            float z;
            z = fmaxf(acc[i][jv + 0] + bb[jv + 0], 0.0f); o.x = sc[jv + 0] * z + sh[jv + 0];
            z = fmaxf(acc[i][jv + 1] + bb[jv + 1], 0.0f); o.y = sc[jv + 1] * z + sh[jv + 1];
            z = fmaxf(acc[i][jv + 2] + bb[jv + 2], 0.0f); o.z = sc[jv + 2] * z + sh[jv + 2];
            z = fmaxf(acc[i][jv + 3] + bb[jv + 3], 0.0f); o.w = sc[jv + 3] * z + sh[jv + 3];
            *(float4*)(crow + jv) = o;
        }
    }
}

// ---------------------------------------------------------------------------
// launch
// ---------------------------------------------------------------------------
extern "C" void kernel_launch(void* const* d_in, const int* in_sizes, int n_in,
                              void* d_out, int out_size)
{
    const float* xyz1   = (const float*)d_in[0];
    const float* xyz2   = (const float*)d_in[1];
    const float* feat1  = (const float*)d_in[2];
    const float* feat2  = (const float*)d_in[3];
    const float* W0     = (const float*)d_in[4];
    const float* b0     = (const float*)d_in[5];
    const float* gamma0 = (const float*)d_in[6];
    const float* beta0  = (const float*)d_in[7];
    const float* mean0  = (const float*)d_in[8];
    const float* var0   = (const float*)d_in[9];
    const float* W1     = (const float*)d_in[10];
    const float* b1     = (const float*)d_in[11];
    const float* gamma1 = (const float*)d_in[12];
    const float* beta1  = (const float*)d_in[13];
    const float* mean1  = (const float*)d_in[14];
    const float* var1   = (const float*)d_in[15];
    float* out = (float*)d_out;

    float* x0 = nullptr;
    float* x1 = nullptr;
    cudaGetSymbolAddress((void**)&x0, g_x0);
    cudaGetSymbolAddress((void**)&x1, g_x1);

    // 1) interpolate + concat
    {
        dim3 grid(N1_ / PPB, B_);
        interp_kernel<<<grid, PPB>>>(xyz1, xyz2, feat1, feat2, x0);
    }
    // 2) layer 0: (M,384) @ (384,256)
    {
        dim3 grid(M_ / GBM, CH_ / GBN);
        gemm_fused<<<grid, 256>>>(x0, W0, b0, gamma0, beta0, mean0, var0,
                                  x1, M_, CH_, CIN_);
    }
    // 3) layer 1: (M,256) @ (256,256) -> out
    {
        dim3 grid(M_ / GBM, CH_ / GBN);
        gemm_fused<<<grid, 256>>>(x1, W1, b1, gamma1, beta1, mean1, var1,
                                  out, M_, CH_, CH_);
    }
}

// round 7
// speedup vs baseline: 1.2098x; 1.2068x over previous
#include <cuda_runtime.h>
#include <cuda_bf16.h>
#include <cstdint>

// ---------------------------------------------------------------------------
// FeaturePropagation, factorized:
//   knn:    3-NN idx+weights per query point (no feature gather)
//   Y2   =  feat2 @ W0[0:256]                     (16384 x 256, raw)
//   x1   =  BN(relu(feat1 @ W0[256:384] + gather_w(Y2) + b0))
//   out  =  BN(relu(x1 @ W1 + b1))
// ---------------------------------------------------------------------------

#define B_   16
#define N1_  4096
#define N2_  1024
#define C1_  128
#define C2_  256
#define CH_  256
#define M_   (B_ * N1_)
#define M2_  (B_ * N2_)
#define BN_EPS 1e-3f

// scratch (allocation-free rule: device globals)
__device__ float g_x1[(size_t)M_ * CH_];    // ~67 MB
__device__ float g_y2[(size_t)M2_ * CH_];   // 16 MB (L2-resident)
__device__ int   g_knn_idx[(size_t)M_ * 3];
__device__ float g_knn_w[(size_t)M_ * 3];

// ---------------------------------------------------------------------------
// Kernel 1: 3-NN search. 2 threads per query point, each scans half the
// candidates; pair-merge via shfl. grid (N1/64, B), block 128.
// ---------------------------------------------------------------------------
#define KPB 64

__global__ __launch_bounds__(128) void knn_kernel(
    const float* __restrict__ xyz1,   // (B, N1, 3)
    const float* __restrict__ xyz2,   // (B, N2, 3)
    int*   __restrict__ knn_idx,      // (M, 3)  global Y2 row indices
    float* __restrict__ knn_w)        // (M, 3)
{
    __shared__ float4 s2[N2_];        // (x, y, z, |p|^2)  16 KB

    const int tid = threadIdx.x;
    const int b   = blockIdx.y;
    const int n   = blockIdx.x * KPB + (tid >> 1);
    const int h   = tid & 1;

    for (int j = tid; j < N2_; j += 128) {
        float x = xyz2[((size_t)b * N2_ + j) * 3 + 0];
        float y = xyz2[((size_t)b * N2_ + j) * 3 + 1];
        float z = xyz2[((size_t)b * N2_ + j) * 3 + 2];
        s2[j] = make_float4(x, y, z, x * x + y * y + z * z);
    }
    __syncthreads();

    const float qx = xyz1[((size_t)b * N1_ + n) * 3 + 0];
    const float qy = xyz1[((size_t)b * N1_ + n) * 3 + 1];
    const float qz = xyz1[((size_t)b * N1_ + n) * 3 + 2];
    const float a2 = qx * qx + qy * qy + qz * qz;

    float d0 = 1e30f, d1 = 1e30f, d2v = 1e30f;
    int   i0 = 0, i1 = 0, i2 = 0;

    const int jbeg = h * (N2_ / 2);
    #pragma unroll 4
    for (int j = jbeg; j < jbeg + N2_ / 2; j++) {
        float4 c = s2[j];
        float ab = qx * c.x + qy * c.y + qz * c.z;
        float d  = fmaxf(fmaf(-2.0f, ab, a2 + c.w), 0.0f);
        if (d < d0) {
            d2v = d1; i2 = i1;
            d1 = d0;  i1 = i0;
            d0 = d;   i0 = j;
        } else if (d < d1) {
            d2v = d1; i2 = i1;
            d1 = d;   i1 = j;
        } else if (d < d2v) {
            d2v = d;  i2 = j;
        }
    }

    // pair-merge: exchange partner's top-3, insert (strict < keeps
    // lower-index-half precedence on ties for the h==0 writer)
    float od[3]; int oi[3];
    od[0] = __shfl_xor_sync(0xffffffffu, d0,  1); oi[0] = __shfl_xor_sync(0xffffffffu, i0, 1);
    od[1] = __shfl_xor_sync(0xffffffffu, d1,  1); oi[1] = __shfl_xor_sync(0xffffffffu, i1, 1);
    od[2] = __shfl_xor_sync(0xffffffffu, d2v, 1); oi[2] = __shfl_xor_sync(0xffffffffu, i2, 1);
    #pragma unroll
    for (int t = 0; t < 3; t++) {
        float d = od[t]; int i = oi[t];
        if (d < d0) {
            d2v = d1; i2 = i1;
            d1 = d0;  i1 = i0;
            d0 = d;   i0 = i;
        } else if (d < d1) {
            d2v = d1; i2 = i1;
            d1 = d;   i1 = i;
        } else if (d < d2v) {
            d2v = d;  i2 = i;
        }
    }

    if (h == 0) {
        float w0 = 1.0f / (d0  + 1e-10f);
        float w1 = 1.0f / (d1  + 1e-10f);
        float w2 = 1.0f / (d2v + 1e-10f);
        float inv = 1.0f / (w0 + w1 + w2);
        const size_t gm = (size_t)b * N1_ + n;
        knn_idx[gm * 3 + 0] = b * N2_ + i0;
        knn_idx[gm * 3 + 1] = b * N2_ + i1;
        knn_idx[gm * 3 + 2] = b * N2_ + i2;
        knn_w[gm * 3 + 0] = w0 * inv;
        knn_w[gm * 3 + 1] = w1 * inv;
        knn_w[gm * 3 + 2] = w2 * inv;
    }
}

// ---------------------------------------------------------------------------
// Double-buffered SGEMM, 128x128x16 tile, 256 threads, 8x8/thread.
// EPI: 0 = raw store, 1 = bias+relu+BN, 2 = Y2-gather + bias+relu+BN
// ---------------------------------------------------------------------------
#define GBM 128
#define GBN 128
#define GBK 16
#define GTM 8
#define GTN 8

template<int EPI>
__global__ __launch_bounds__(256) void gemm_k(
    const float* __restrict__ A, const float* __restrict__ W,
    const float* __restrict__ bias, const float* __restrict__ gamma,
    const float* __restrict__ beta, const float* __restrict__ mean,
    const float* __restrict__ var,
    const float* __restrict__ Y2,
    const int*   __restrict__ knn_idx,
    const float* __restrict__ knn_w,
    float* __restrict__ C, int M, int N, int K)
{
    __shared__ float As[2][GBK][GBM];
    __shared__ float Bs[2][GBK][GBN];
    __shared__ int   sidx[3 * GBM];
    __shared__ float swt[3 * GBM];

    const int tid = threadIdx.x;
    const int tx = tid & 15;
    const int ty = tid >> 4;
    const int row0 = blockIdx.x * GBM;
    const int col0 = blockIdx.y * GBN;

    const int aRow = tid >> 2;            // 0..63 (+64)
    const int aCol = (tid & 3) << 2;      // 0,4,8,12
    const int bRow = tid >> 5;            // 0..7 (+8)
    const int bCol = (tid & 31) << 2;     // 0..124

    float acc[GTM][GTN];
    #pragma unroll
    for (int i = 0; i < GTM; i++)
        #pragma unroll
        for (int j = 0; j < GTN; j++) acc[i][j] = 0.0f;

    const int ntiles = K / GBK;

    // prologue: tile 0 straight into buffer 0
    {
        #pragma unroll
        for (int r = 0; r < 2; r++) {
            int m = aRow + r * 64;
            float4 v = *(const float4*)(A + (size_t)(row0 + m) * K + aCol);
            As[0][aCol + 0][m] = v.x;
            As[0][aCol + 1][m] = v.y;
            As[0][aCol + 2][m] = v.z;
            As[0][aCol + 3][m] = v.w;
        }
        #pragma unroll
        for (int r = 0; r < 2; r++) {
            int kk = bRow + r * 8;
            *(float4*)(&Bs[0][kk][bCol]) =
                *(const float4*)(W + (size_t)kk * N + col0 + bCol);
        }
    }
    __syncthreads();

    float4 aNxt[2], bNxt[2];
    for (int kt = 0; kt < ntiles; kt++) {
        const int cur = kt & 1;
        const bool more = (kt + 1 < ntiles);
        if (more) {
            const int k0 = (kt + 1) * GBK;
            aNxt[0] = *(const float4*)(A + (size_t)(row0 + aRow)      * K + k0 + aCol);
            aNxt[1] = *(const float4*)(A + (size_t)(row0 + aRow + 64) * K + k0 + aCol);
            bNxt[0] = *(const float4*)(W + (size_t)(k0 + bRow)     * N + col0 + bCol);
            bNxt[1] = *(const float4*)(W + (size_t)(k0 + bRow + 8) * N + col0 + bCol);
        }

        #pragma unroll
        for (int kk = 0; kk < GBK; kk++) {
            float af[GTM], bf[GTN];
            #pragma unroll
            for (int i = 0; i < GTM; i++) af[i] = As[cur][kk][ty * GTM + i];
            #pragma unroll
            for (int j = 0; j < GTN; j++) bf[j] = Bs[cur][kk][tx * GTN + j];
            #pragma unroll
            for (int i = 0; i < GTM; i++)
                #pragma unroll
                for (int j = 0; j < GTN; j++)
                    acc[i][j] = fmaf(af[i], bf[j], acc[i][j]);
        }

        if (more) {
            const int nxt = cur ^ 1;
            As[nxt][aCol + 0][aRow]      = aNxt[0].x;
            As[nxt][aCol + 1][aRow]      = aNxt[0].y;
            As[nxt][aCol + 2][aRow]      = aNxt[0].z;
            As[nxt][aCol + 3][aRow]      = aNxt[0].w;
            As[nxt][aCol + 0][aRow + 64] = aNxt[1].x;
            As[nxt][aCol + 1][aRow + 64] = aNxt[1].y;
            As[nxt][aCol + 2][aRow + 64] = aNxt[1].z;
            As[nxt][aCol + 3][aRow + 64] = aNxt[1].w;
            *(float4*)(&Bs[nxt][bRow][bCol])     = bNxt[0];
            *(float4*)(&Bs[nxt][bRow + 8][bCol]) = bNxt[1];
            __syncthreads();
        }
    }

    // ---- EPI==2: interpolated contribution gathered from Y2 ----
    if (EPI == 2) {
        __syncthreads();   // all compute done before reusing bars/shared flow
        for (int i = tid; i < 3 * GBM; i += 256) {
            sidx[i] = knn_idx[(size_t)row0 * 3 + i];
            swt[i]  = knn_w[(size_t)row0 * 3 + i];
        }
        __syncthreads();
        #pragma unroll
        for (int i = 0; i < GTM; i++) {
            const int ml = ty * GTM + i;
            #pragma unroll
            for (int t = 0; t < 3; t++) {
                const int   gi = sidx[ml * 3 + t];
                const float wt = swt[ml * 3 + t];
                const float* yr = Y2 + (size_t)gi * CH_ + col0 + tx * GTN;
                float4 v0 = *(const float4*)(yr);
                float4 v1 = *(const float4*)(yr + 4);
                acc[i][0] = fmaf(wt, v0.x, acc[i][0]);
                acc[i][1] = fmaf(wt, v0.y, acc[i][1]);
                acc[i][2] = fmaf(wt, v0.z, acc[i][2]);
                acc[i][3] = fmaf(wt, v0.w, acc[i][3]);
                acc[i][4] = fmaf(wt, v1.x, acc[i][4]);
                acc[i][5] = fmaf(wt, v1.y, acc[i][5]);
                acc[i][6] = fmaf(wt, v1.z, acc[i][6]);
                acc[i][7] = fmaf(wt, v1.w, acc[i][7]);
            }
        }
    }

    if (EPI == 0) {
        // raw store
        #pragma unroll
        for (int i = 0; i < GTM; i++) {
            float* crow = C + (size_t)(row0 + ty * GTM + i) * N + col0 + tx * GTN;
            #pragma unroll
            for (int jv = 0; jv < GTN; jv += 4) {
                float4 o = { acc[i][jv], acc[i][jv + 1], acc[i][jv + 2], acc[i][jv + 3] };
                *(float4*)(crow + jv) = o;
            }
        }
    } else {
        float sc[GTN], sh[GTN], bb[GTN];
        #pragma unroll
        for (int j = 0; j < GTN; j++) {
            int nn = col0 + tx * GTN + j;
            float s = gamma[nn] * rsqrtf(var[nn] + BN_EPS);
            sc[j] = s;
            sh[j] = beta[nn] - mean[nn] * s;
            bb[j] = bias[nn];
        }
        #pragma unroll
        for (int i = 0; i < GTM; i++) {
            float* crow = C + (size_t)(row0 + ty * GTM + i) * N + col0 + tx * GTN;
            #pragma unroll
            for (int jv = 0; jv < GTN; jv += 4) {
                float4 o; float z;
                z = fmaxf(acc[i][jv + 0] + bb[jv + 0], 0.0f); o.x = sc[jv + 0] * z + sh[jv + 0];
                z = fmaxf(acc[i][jv + 1] + bb[jv + 1], 0.0f); o.y = sc[jv + 1] * z + sh[jv + 1];
                z = fmaxf(acc[i][jv + 2] + bb[jv + 2], 0.0f); o.z = sc[jv + 2] * z + sh[jv + 2];
                z = fmaxf(acc[i][jv + 3] + bb[jv + 3], 0.0f); o.w = sc[jv + 3] * z + sh[jv + 3];
                *(float4*)(crow + jv) = o;
            }
        }
    }
}

// ---------------------------------------------------------------------------
// launch
// ---------------------------------------------------------------------------
extern "C" void kernel_launch(void* const* d_in, const int* in_sizes, int n_in,
                              void* d_out, int out_size)
{
    const float* xyz1   = (const float*)d_in[0];
    const float* xyz2   = (const float*)d_in[1];
    const float* feat1  = (const float*)d_in[2];
    const float* feat2  = (const float*)d_in[3];
    const float* W0     = (const float*)d_in[4];
    const float* b0     = (const float*)d_in[5];
    const float* gamma0 = (const float*)d_in[6];
    const float* beta0  = (const float*)d_in[7];
    const float* mean0  = (const float*)d_in[8];
    const float* var0   = (const float*)d_in[9];
    const float* W1     = (const float*)d_in[10];
    const float* b1     = (const float*)d_in[11];
    const float* gamma1 = (const float*)d_in[12];
    const float* beta1  = (const float*)d_in[13];
    const float* mean1  = (const float*)d_in[14];
    const float* var1   = (const float*)d_in[15];
    float* out = (float*)d_out;

    float* x1 = nullptr;  float* y2 = nullptr;
    int* kidx = nullptr;  float* kw = nullptr;
    cudaGetSymbolAddress((void**)&x1,   g_x1);
    cudaGetSymbolAddress((void**)&y2,   g_y2);
    cudaGetSymbolAddress((void**)&kidx, g_knn_idx);
    cudaGetSymbolAddress((void**)&kw,   g_knn_w);

    // 1) 3-NN indices + weights
    {
        dim3 grid(N1_ / KPB, B_);
        knn_kernel<<<grid, 128>>>(xyz1, xyz2, kidx, kw);
    }
    // 2) Y2 = feat2 @ W0[0:256]   (raw)
    {
        dim3 grid(M2_ / GBM, CH_ / GBN);
        gemm_k<0><<<grid, 256>>>(feat2, W0, nullptr, nullptr, nullptr, nullptr,
                                 nullptr, nullptr, nullptr, nullptr,
                                 y2, M2_, CH_, C2_);
    }
    // 3) x1 = BN(relu(feat1 @ W0[256:384] + gather(Y2) + b0))
    {
        dim3 grid(M_ / GBM, CH_ / GBN);
        gemm_k<2><<<grid, 256>>>(feat1, W0 + (size_t)C2_ * CH_,
                                 b0, gamma0, beta0, mean0, var0,
                                 y2, kidx, kw,
                                 x1, M_, CH_, C1_);
    }
    // 4) out = BN(relu(x1 @ W1 + b1))
    {
        dim3 grid(M_ / GBM, CH_ / GBN);
        gemm_k<1><<<grid, 256>>>(x1, W1, b1, gamma1, beta1, mean1, var1,
                                 nullptr, nullptr, nullptr,
                                 out, M_, CH_, CH_);
    }
}